// round 15
// baseline (speedup 1.0000x reference)
#include <cuda_runtime.h>
#include <cuda_bf16.h>
#include <math.h>
#include <stdint.h>

#define NNODES 100000
#define NEDGES 1600000
#define NB 16
#define HID 64
#define OUTD 128
#define NCHUNKS (NEDGES / 32)     // 50000 edge warp-chunks
#define EDGE_NW 6                 // warps per edge block
#define EDGE_BLOCKS (148 * 2)     // 2 blocks/SM
#define NODE_CHUNKS (NNODES / 32) // 3125
#define NODE_NW 4
#define NODE_BLOCKS ((NODE_CHUNKS + NODE_NW - 1) / NODE_NW)  // 782

typedef unsigned long long ull;

__device__ float g_agg[(size_t)NNODES * HID];

// ---------------------------------------------------------------------------
// Edge-kernel SMEM layout (bytes) — compact 3-pass split operands
// ---------------------------------------------------------------------------
#define OFF_B1V  0                                  // 64 f32
#define OFF_B2V  256                                // 64 f32
#define OFF_CON  512                                // 192 f32 -> ends 1280
#define OFF_W1T  1536                               // 64 x 144B  [W1h|W1l] K=64
#define OFF_W2T  (OFF_W1T + 64*144)                 // 64 x 272B  [W2h|W2l] K=128
#define OFF_A1   (OFF_W2T + 64*272)                 // NW x 32 x 144B  [Fh|Fl]
#define OFF_A2   (OFF_A1 + EDGE_NW*32*144)          // NW x 32 x 272B  [Ph|Pl]
#define SMEM_BYTES (OFF_A2 + EDGE_NW*32*272)        // 108032

// ---------------------------------------------------------------------------
// Node-kernel SMEM layout (unchanged, proven)
// ---------------------------------------------------------------------------
#define NOD_NPB  0
#define NOD_ZNB  512
#define NOD_CON  768
#define NOD_ZN   1536
#define NOD_NP   (NOD_ZN + 64*208)
#define NOD_A0   (NOD_NP + 128*528)
#define NOD_X    (NOD_A0 + NODE_NW*32*272)
#define NOD_SMEM (NOD_X + NODE_NW*32*528)           // 184832

// ---------------------------------------------------------------------------
// helpers
// ---------------------------------------------------------------------------
__device__ __forceinline__ float silu_f(float x) {
    return __fdividef(x, 1.0f + __expf(-x));
}
__device__ __forceinline__ float trunc_hi(float x) {
    return __uint_as_float(__float_as_uint(x) & 0xFFFF0000u);
}
__device__ __forceinline__ unsigned short hi16(float x) {
    return (unsigned short)(__float_as_uint(x) >> 16);
}
__device__ __forceinline__ unsigned short lo_bf16(float x) {
    return __bfloat16_as_ushort(__float2bfloat16_rn(x - trunc_hi(x)));
}
__device__ __forceinline__ uint32_t pack_hi2(float a, float b) {
    uint32_t r;
    asm("prmt.b32 %0, %1, %2, 0x7632;"
        : "=r"(r) : "r"(__float_as_uint(a)), "r"(__float_as_uint(b)));
    return r;
}
__device__ __forceinline__ uint32_t pack_lo2(float a, float b) {
    float la = a - trunc_hi(a), lb = b - trunc_hi(b);
    uint32_t r;
    asm("cvt.rn.bf16x2.f32 %0, %1, %2;" : "=r"(r) : "f"(lb), "f"(la));
    return r;
}
__device__ __forceinline__ void mma16816(float& d0, float& d1, float& d2, float& d3,
                                         uint32_t a0, uint32_t a1, uint32_t a2, uint32_t a3,
                                         uint32_t b0, uint32_t b1) {
    asm volatile(
        "mma.sync.aligned.m16n8k16.row.col.f32.bf16.bf16.f32 "
        "{%0,%1,%2,%3}, {%4,%5,%6,%7}, {%8,%9}, {%0,%1,%2,%3};"
        : "+f"(d0), "+f"(d1), "+f"(d2), "+f"(d3)
        : "r"(a0), "r"(a1), "r"(a2), "r"(a3), "r"(b0), "r"(b1));
}

#define SH_C0 0.28209479177387814f
#define SH_C1 0.4886025119029199f
#define SH_C2 1.0925484305920792f
#define SH_C3 0.31539156525252005f
#define SH_C4 0.5462742152960396f

__device__ __forceinline__ void build_feat32(
    float dist, float ux, float uy, float uz,
    const float* s_c, const float* s_wd, const float* s_shb, const float* s_shw,
    float feat[32])
{
#pragma unroll
    for (int k = 0; k < NB; k++) {
        const float tt = dist - s_c[k];
        feat[k] = __expf(-fabsf(s_wd[k]) * tt * tt);
    }
    float sh[9];
    sh[0] = SH_C0;
    sh[1] = SH_C1 * uy;
    sh[2] = SH_C1 * uz;
    sh[3] = SH_C1 * ux;
    sh[4] = SH_C2 * ux * uy;
    sh[5] = SH_C2 * uy * uz;
    sh[6] = SH_C3 * (2.0f * uz * uz - ux * ux - uy * uy);
    sh[7] = SH_C2 * ux * uz;
    sh[8] = SH_C4 * (ux * ux - uy * uy);
#pragma unroll
    for (int k = 0; k < NB; k++) {
        float a = s_shb[k];
#pragma unroll
        for (int j = 0; j < 9; j++) a += sh[j] * s_shw[j * NB + k];
        feat[NB + k] = a;
    }
}

// write [Fh(64B) | Fl(64B)]
__device__ __forceinline__ void write_split_row64(char* row, const float feat[32]) {
#pragma unroll
    for (int c = 0; c < 4; c++) {
        uint4 hi, lo;
        hi.x = pack_hi2(feat[8 * c + 0], feat[8 * c + 1]);
        hi.y = pack_hi2(feat[8 * c + 2], feat[8 * c + 3]);
        hi.z = pack_hi2(feat[8 * c + 4], feat[8 * c + 5]);
        hi.w = pack_hi2(feat[8 * c + 6], feat[8 * c + 7]);
        lo.x = pack_lo2(feat[8 * c + 0], feat[8 * c + 1]);
        lo.y = pack_lo2(feat[8 * c + 2], feat[8 * c + 3]);
        lo.z = pack_lo2(feat[8 * c + 4], feat[8 * c + 5]);
        lo.w = pack_lo2(feat[8 * c + 6], feat[8 * c + 7]);
        *reinterpret_cast<uint4*>(row + c * 16)      = hi;
        *reinterpret_cast<uint4*>(row + 64 + c * 16) = lo;
    }
}

// for node kernel ([Fh|Fh|Fl] stride-272 rows)
__device__ __forceinline__ void write_split_row96(char* row, const float feat[32]) {
#pragma unroll
    for (int c = 0; c < 4; c++) {
        uint4 hi, lo;
        hi.x = pack_hi2(feat[8 * c + 0], feat[8 * c + 1]);
        hi.y = pack_hi2(feat[8 * c + 2], feat[8 * c + 3]);
        hi.z = pack_hi2(feat[8 * c + 4], feat[8 * c + 5]);
        hi.w = pack_hi2(feat[8 * c + 6], feat[8 * c + 7]);
        lo.x = pack_lo2(feat[8 * c + 0], feat[8 * c + 1]);
        lo.y = pack_lo2(feat[8 * c + 2], feat[8 * c + 3]);
        lo.z = pack_lo2(feat[8 * c + 4], feat[8 * c + 5]);
        lo.w = pack_lo2(feat[8 * c + 6], feat[8 * c + 7]);
        *reinterpret_cast<uint4*>(row + c * 16)       = hi;
        *reinterpret_cast<uint4*>(row + 64 + c * 16)  = hi;
        *reinterpret_cast<uint4*>(row + 128 + c * 16) = lo;
    }
}

// ---------------------------------------------------------------------------
__global__ void zero_agg_kernel() {
    size_t i = (size_t)blockIdx.x * blockDim.x + threadIdx.x;
    size_t n4 = (size_t)NNODES * HID / 4;
    if (i < n4) reinterpret_cast<float4*>(g_agg)[i] = make_float4(0.f, 0.f, 0.f, 0.f);
}

// ---------------------------------------------------------------------------
// Edge kernel: warp-per-32-edges, 3-pass split GEMMs, cross-chunk prefetch.
// ---------------------------------------------------------------------------
__global__ __launch_bounds__(32 * EDGE_NW, 2) void edge_kernel(
    const float* __restrict__ pos,
    const int*   __restrict__ ei,
    const float* __restrict__ rbf_c,
    const float* __restrict__ rbf_w,
    const float* __restrict__ sh_w,
    const float* __restrict__ sh_b,
    const float* __restrict__ w1,
    const float* __restrict__ b1,
    const float* __restrict__ w2,
    const float* __restrict__ b2)
{
    extern __shared__ char smem[];
    const int tid = threadIdx.x;
    const int wid = tid >> 5;
    const int lane = tid & 31;
    const int NT = 32 * EDGE_NW;

    for (int i = tid; i < 64 * 64; i += NT) {
        const int n = i >> 6, k = i & 63;
        unsigned short v;
        if (k < 32) v = hi16(w1[k * HID + n]);
        else        v = lo_bf16(w1[(k - 32) * HID + n]);
        *reinterpret_cast<unsigned short*>(smem + OFF_W1T + n * 144 + k * 2) = v;
    }
    for (int i = tid; i < 64 * 128; i += NT) {
        const int n = i >> 7, k = i & 127;
        unsigned short v;
        if (k < 64) v = hi16(w2[k * HID + n]);
        else        v = lo_bf16(w2[(k - 64) * HID + n]);
        *reinterpret_cast<unsigned short*>(smem + OFF_W2T + n * 272 + k * 2) = v;
    }
    float* s_b1v = reinterpret_cast<float*>(smem + OFF_B1V);
    float* s_b2v = reinterpret_cast<float*>(smem + OFF_B2V);
    float* s_con = reinterpret_cast<float*>(smem + OFF_CON);
    if (tid < HID) { s_b1v[tid] = b1[tid]; s_b2v[tid] = b2[tid]; }
    if (tid < NB) {
        s_con[tid]      = rbf_c[tid];
        s_con[16 + tid] = rbf_w[tid];
        s_con[32 + tid] = sh_b[tid];
    }
    for (int i = tid; i < 9 * NB; i += NT) s_con[48 + i] = sh_w[i];
    __syncthreads();

    const float* s_c   = s_con;
    const float* s_wd  = s_con + 16;
    const float* s_shb = s_con + 32;
    const float* s_shw = s_con + 48;

    char* A1w = smem + OFF_A1 + wid * 32 * 144;
    char* A2w = smem + OFF_A2 + wid * 32 * 272;
    char* PFw = A2w;

    const int r0 = lane >> 2;
    const int qp = lane & 3;
    const int xr = (lane >> 3) & 3;
    const int stride = gridDim.x * EDGE_NW;

    int chunk = blockIdx.x * EDGE_NW + wid;
    if (chunk >= NCHUNKS) return;

    // preload first chunk's indices + positions
    int cs = ei[chunk * 32 + lane];
    int cd = ei[NEDGES + chunk * 32 + lane];
    float psx = pos[3 * cs + 0], psy = pos[3 * cs + 1], psz = pos[3 * cs + 2];
    float pdx = pos[3 * cd + 0], pdy = pos[3 * cd + 1], pdz = pos[3 * cd + 2];

    for (; chunk < NCHUNKS; chunk += stride) {
        // ---- prefetch next chunk's indices ----
        const int nchunk = chunk + stride;
        const int pidx = (nchunk < NCHUNKS) ? nchunk * 32 + lane : lane;
        const int ns = ei[pidx];
        const int nd = ei[NEDGES + pidx];

        // ---- features for current chunk (all operands already in regs) ----
        const float rx = pdx - psx;
        const float ry = pdy - psy;
        const float rz = pdz - psz;
        float dist = fmaxf(sqrtf(rx * rx + ry * ry + rz * rz), 1e-6f);
        const float inv = __fdividef(1.0f, dist);

        float feat[32];
        build_feat32(dist, rx * inv, ry * inv, rz * inv, s_c, s_wd, s_shb, s_shw, feat);
        write_split_row64(A1w + lane * 144, feat);

        // ---- prefetch next chunk's positions (latency hidden under GEMMs) ----
        const float npsx = pos[3 * ns + 0], npsy = pos[3 * ns + 1], npsz = pos[3 * ns + 2];
        const float npdx = pos[3 * nd + 0], npdy = pos[3 * nd + 1], npdz = pos[3 * nd + 2];

        __syncwarp();

        float dacc[2][8][4];
#pragma unroll
        for (int mt = 0; mt < 2; mt++)
#pragma unroll
            for (int nt = 0; nt < 8; nt++)
#pragma unroll
                for (int j = 0; j < 4; j++) dacc[mt][nt][j] = 0.0f;

        // ---- GEMM1: 3 passes (Fh@W1h, Fh@W1l, Fl@W1h) ----
#pragma unroll
        for (int pass = 0; pass < 3; pass++) {
            const int aoff = (pass == 2) ? 64 : 0;
            const int boff = (pass == 1) ? 64 : 0;
#pragma unroll
            for (int kt = 0; kt < 2; kt++) {
                uint32_t a[2][4];
#pragma unroll
                for (int mt = 0; mt < 2; mt++) {
                    const char* base = A1w + (mt * 16 + r0) * 144 + aoff + kt * 32 + qp * 4;
                    a[mt][0] = *reinterpret_cast<const uint32_t*>(base);
                    a[mt][1] = *reinterpret_cast<const uint32_t*>(base + 8 * 144);
                    a[mt][2] = *reinterpret_cast<const uint32_t*>(base + 16);
                    a[mt][3] = *reinterpret_cast<const uint32_t*>(base + 8 * 144 + 16);
                }
#pragma unroll
                for (int nt = 0; nt < 8; nt++) {
                    const char* bb = smem + OFF_W1T + (nt * 8 + r0) * 144 + boff + kt * 32 + qp * 4;
                    const uint32_t b0 = *reinterpret_cast<const uint32_t*>(bb);
                    const uint32_t bb1 = *reinterpret_cast<const uint32_t*>(bb + 16);
                    mma16816(dacc[0][nt][0], dacc[0][nt][1], dacc[0][nt][2], dacc[0][nt][3],
                             a[0][0], a[0][1], a[0][2], a[0][3], b0, bb1);
                    mma16816(dacc[1][nt][0], dacc[1][nt][1], dacc[1][nt][2], dacc[1][nt][3],
                             a[1][0], a[1][1], a[1][2], a[1][3], b0, bb1);
                }
            }
        }

        // ---- epilogue1: bias + silu + split -> A2 [Ph|Pl] ----
#pragma unroll
        for (int nt = 0; nt < 8; nt++) {
            const float2 bp = *reinterpret_cast<const float2*>(s_b1v + nt * 8 + 2 * qp);
#pragma unroll
            for (int mt = 0; mt < 2; mt++) {
#pragma unroll
                for (int sdx = 0; sdx < 2; sdx++) {
                    const float p0 = silu_f(dacc[mt][nt][2 * sdx + 0] + bp.x);
                    const float p1 = silu_f(dacc[mt][nt][2 * sdx + 1] + bp.y);
                    const int rloc = mt * 16 + sdx * 8 + r0;
                    char* prow = A2w + rloc * 272;
                    const int cb = nt * 16 + qp * 4;
                    *reinterpret_cast<uint32_t*>(prow + cb)       = pack_hi2(p0, p1);
                    *reinterpret_cast<uint32_t*>(prow + 128 + cb) = pack_lo2(p0, p1);
                }
            }
        }
        __syncwarp();

#pragma unroll
        for (int mt = 0; mt < 2; mt++)
#pragma unroll
            for (int nt = 0; nt < 8; nt++)
#pragma unroll
                for (int j = 0; j < 4; j++) dacc[mt][nt][j] = 0.0f;

        // ---- GEMM2: 3 passes (Ph@W2h, Ph@W2l, Pl@W2h) ----
#pragma unroll
        for (int pass = 0; pass < 3; pass++) {
            const int aoff = (pass == 2) ? 128 : 0;
            const int boff = (pass == 1) ? 128 : 0;
#pragma unroll
            for (int kt = 0; kt < 4; kt++) {
                uint32_t a[2][4];
#pragma unroll
                for (int mt = 0; mt < 2; mt++) {
                    const char* base = A2w + (mt * 16 + r0) * 272 + aoff + kt * 32 + qp * 4;
                    a[mt][0] = *reinterpret_cast<const uint32_t*>(base);
                    a[mt][1] = *reinterpret_cast<const uint32_t*>(base + 8 * 272);
                    a[mt][2] = *reinterpret_cast<const uint32_t*>(base + 16);
                    a[mt][3] = *reinterpret_cast<const uint32_t*>(base + 8 * 272 + 16);
                }
#pragma unroll
                for (int nt = 0; nt < 8; nt++) {
                    const char* bb = smem + OFF_W2T + (nt * 8 + r0) * 272 + boff + kt * 32 + qp * 4;
                    const uint32_t b0 = *reinterpret_cast<const uint32_t*>(bb);
                    const uint32_t bb1 = *reinterpret_cast<const uint32_t*>(bb + 16);
                    mma16816(dacc[0][nt][0], dacc[0][nt][1], dacc[0][nt][2], dacc[0][nt][3],
                             a[0][0], a[0][1], a[0][2], a[0][3], b0, bb1);
                    mma16816(dacc[1][nt][0], dacc[1][nt][1], dacc[1][nt][2], dacc[1][nt][3],
                             a[1][0], a[1][1], a[1][2], a[1][3], b0, bb1);
                }
            }
        }
        __syncwarp();

        // ---- epilogue2: bias -> pf staging (swizzled) ----
#pragma unroll
        for (int nt = 0; nt < 8; nt++) {
            const float2 bp = *reinterpret_cast<const float2*>(s_b2v + nt * 8 + 2 * qp);
            const int g = (qp >> 1) + 2 * nt;
            const int gsub = (qp & 1) << 3;
#pragma unroll
            for (int mt = 0; mt < 2; mt++) {
#pragma unroll
                for (int sdx = 0; sdx < 2; sdx++) {
                    const int rloc = mt * 16 + sdx * 8 + r0;
                    float2 v;
                    v.x = dacc[mt][nt][2 * sdx + 0] + bp.x;
                    v.y = dacc[mt][nt][2 * sdx + 1] + bp.y;
                    const int gs = g ^ ((rloc >> 3) & 3);
                    *reinterpret_cast<float2*>(PFw + rloc * 272 + gs * 16 + gsub) = v;
                }
            }
        }
        __syncwarp();

        // ---- scatter (current source index held in reg) ----
        {
            const char* myrow = PFw + lane * 272;
            float* ap = g_agg + (size_t)cs * HID;
#pragma unroll
            for (int i = 0; i < 16; i++) {
                const float4 v = *reinterpret_cast<const float4*>(myrow + ((i ^ xr) << 4));
                asm volatile("red.global.add.v4.f32 [%0], {%1, %2, %3, %4};"
                             :: "l"(ap + 4 * i), "f"(v.x), "f"(v.y), "f"(v.z), "f"(v.w)
                             : "memory");
            }
        }
        __syncwarp();

        // rotate prefetched state
        cs = ns; cd = nd;
        psx = npsx; psy = npsy; psz = npsz;
        pdx = npdx; pdy = npdy; pdz = npdz;
    }
}

// ---------------------------------------------------------------------------
// Node kernel (unchanged from R9/R10 — proven)
// ---------------------------------------------------------------------------
__global__ __launch_bounds__(128) void node_kernel(
    const float* __restrict__ pos,
    const float* __restrict__ zinc,
    const float* __restrict__ rbf_c,
    const float* __restrict__ rbf_w,
    const float* __restrict__ sh_w,
    const float* __restrict__ sh_b,
    const float* __restrict__ zn_w,
    const float* __restrict__ zn_b,
    const float* __restrict__ np_w,
    const float* __restrict__ np_b,
    const float* __restrict__ ln_g,
    const float* __restrict__ ln_b,
    float* __restrict__ out)
{
    extern __shared__ char smem[];
    const int tid = threadIdx.x;
    const int wid = tid >> 5;
    const int lane = tid & 31;

    for (int i = tid; i < 64 * 96; i += 128) {
        const int n = i / 96, k = i % 96;
        unsigned short v;
        if (k < 32)      v = hi16(zn_w[k * HID + n]);
        else if (k < 64) v = lo_bf16(zn_w[(k - 32) * HID + n]);
        else             v = hi16(zn_w[(k - 64) * HID + n]);
        *reinterpret_cast<unsigned short*>(smem + NOD_ZN + n * 208 + k * 2) = v;
    }
    for (int i = tid; i < 128 * 128; i += 128) {
        const int k = i >> 7, n = i & 127;
        const float w = np_w[k * OUTD + n];
        *reinterpret_cast<unsigned short*>(smem + NOD_NP + n * 528 + k * 2)       = hi16(w);
        *reinterpret_cast<unsigned short*>(smem + NOD_NP + n * 528 + 256 + k * 2) = lo_bf16(w);
    }
    float* s_npb = reinterpret_cast<float*>(smem + NOD_NPB);
    float* s_znb = reinterpret_cast<float*>(smem + NOD_ZNB);
    float* s_con = reinterpret_cast<float*>(smem + NOD_CON);
    if (tid < OUTD) s_npb[tid] = np_b[tid];
    if (tid < HID)  s_znb[tid] = zn_b[tid];
    if (tid < NB) {
        s_con[tid]      = rbf_c[tid];
        s_con[16 + tid] = rbf_w[tid];
        s_con[32 + tid] = sh_b[tid];
    }
    for (int i = tid; i < 9 * NB; i += 128) s_con[48 + i] = sh_w[i];
    __syncthreads();

    const int chunk = blockIdx.x * NODE_NW + wid;
    if (chunk >= NODE_CHUNKS) return;

    const float* s_c   = s_con;
    const float* s_wd  = s_con + 16;
    const float* s_shb = s_con + 32;
    const float* s_shw = s_con + 48;

    char* A0w = smem + NOD_A0 + wid * 32 * 272;
    char* Xw  = smem + NOD_X  + wid * 32 * 528;

    const int r0 = lane >> 2;
    const int qp = lane & 3;
    const int node = chunk * 32 + lane;

    {
        const float rx = pos[3 * node + 0] - __ldg(&zinc[0]);
        const float ry = pos[3 * node + 1] - __ldg(&zinc[1]);
        const float rz = pos[3 * node + 2] - __ldg(&zinc[2]);
        float dist = fmaxf(sqrtf(rx * rx + ry * ry + rz * rz), 1e-6f);
        const float inv = __fdividef(1.0f, dist);
        float feat[32];
        build_feat32(dist, rx * inv, ry * inv, rz * inv, s_c, s_wd, s_shb, s_shw, feat);
        write_split_row96(A0w + lane * 272, feat);
    }

    {
        const float* ab = g_agg + (size_t)(chunk * 32) * HID;
        const int f = lane & 15;
#pragma unroll
        for (int i = 0; i < 16; i++) {
            const int r = i * 2 + (lane >> 4);
            const float4 v = *reinterpret_cast<const float4*>(ab + r * HID + f * 4);
            uint2 hi, lo;
            hi.x = pack_hi2(v.x, v.y); hi.y = pack_hi2(v.z, v.w);
            lo.x = pack_lo2(v.x, v.y); lo.y = pack_lo2(v.z, v.w);
            *reinterpret_cast<uint2*>(Xw + r * 528 + f * 8)       = hi;
            *reinterpret_cast<uint2*>(Xw + r * 528 + 256 + f * 8) = lo;
        }
    }
    __syncwarp();

    {
        float dz[2][8][4];
#pragma unroll
        for (int mt = 0; mt < 2; mt++)
#pragma unroll
            for (int nt = 0; nt < 8; nt++)
#pragma unroll
                for (int j = 0; j < 4; j++) dz[mt][nt][j] = 0.0f;

#pragma unroll
        for (int kt = 0; kt < 6; kt++) {
            uint32_t a[2][4];
#pragma unroll
            for (int mt = 0; mt < 2; mt++) {
                const char* base = A0w + (mt * 16 + r0) * 272 + kt * 32 + qp * 4;
                a[mt][0] = *reinterpret_cast<const uint32_t*>(base);
                a[mt][1] = *reinterpret_cast<const uint32_t*>(base + 8 * 272);
                a[mt][2] = *reinterpret_cast<const uint32_t*>(base + 16);
                a[mt][3] = *reinterpret_cast<const uint32_t*>(base + 8 * 272 + 16);
            }
#pragma unroll
            for (int nt = 0; nt < 8; nt++) {
                const char* bb = smem + NOD_ZN + (nt * 8 + r0) * 208 + kt * 32 + qp * 4;
                const uint32_t b0 = *reinterpret_cast<const uint32_t*>(bb);
                const uint32_t bb1 = *reinterpret_cast<const uint32_t*>(bb + 16);
                mma16816(dz[0][nt][0], dz[0][nt][1], dz[0][nt][2], dz[0][nt][3],
                         a[0][0], a[0][1], a[0][2], a[0][3], b0, bb1);
                mma16816(dz[1][nt][0], dz[1][nt][1], dz[1][nt][2], dz[1][nt][3],
                         a[1][0], a[1][1], a[1][2], a[1][3], b0, bb1);
            }
        }

#pragma unroll
        for (int nt = 0; nt < 8; nt++) {
            const float2 bp = *reinterpret_cast<const float2*>(s_znb + nt * 8 + 2 * qp);
#pragma unroll
            for (int mt = 0; mt < 2; mt++) {
#pragma unroll
                for (int sdx = 0; sdx < 2; sdx++) {
                    const float p0 = silu_f(dz[mt][nt][2 * sdx + 0] + bp.x);
                    const float p1 = silu_f(dz[mt][nt][2 * sdx + 1] + bp.y);
                    const int rloc = mt * 16 + sdx * 8 + r0;
                    const int c = nt * 8 + qp * 2;
                    *reinterpret_cast<uint32_t*>(Xw + rloc * 528 + 128 + c * 2) =
                        pack_hi2(p0, p1);
                    *reinterpret_cast<uint32_t*>(Xw + rloc * 528 + 384 + c * 2) =
                        pack_lo2(p0, p1);
                }
            }
        }
    }
    __syncwarp();

    float dacc[2][8][4];
    float sum[4], sq[4], mu[4], rs[4];

#pragma unroll
    for (int half = 0; half < 2; half++) {
#pragma unroll
        for (int mt = 0; mt < 2; mt++)
#pragma unroll
            for (int nt = 0; nt < 8; nt++)
#pragma unroll
                for (int j = 0; j < 4; j++) dacc[mt][nt][j] = 0.0f;

#pragma unroll
        for (int pass = 0; pass < 3; pass++) {
            const int aoff = (pass == 2) ? 256 : 0;
            const int boff = (pass == 1) ? 256 : 0;
#pragma unroll
            for (int kt = 0; kt < 8; kt++) {
                uint32_t a[2][4];
#pragma unroll
                for (int mt = 0; mt < 2; mt++) {
                    const char* base = Xw + (mt * 16 + r0) * 528 + aoff + kt * 32 + qp * 4;
                    a[mt][0] = *reinterpret_cast<const uint32_t*>(base);
                    a[mt][1] = *reinterpret_cast<const uint32_t*>(base + 8 * 528);
                    a[mt][2] = *reinterpret_cast<const uint32_t*>(base + 16);
                    a[mt][3] = *reinterpret_cast<const uint32_t*>(base + 8 * 528 + 16);
                }
#pragma unroll
                for (int nt = 0; nt < 8; nt++) {
                    const char* bb = smem + NOD_NP +
                        (half * 64 + nt * 8 + r0) * 528 + boff + kt * 32 + qp * 4;
                    const uint32_t b0 = *reinterpret_cast<const uint32_t*>(bb);
                    const uint32_t bb1 = *reinterpret_cast<const uint32_t*>(bb + 16);
                    mma16816(dacc[0][nt][0], dacc[0][nt][1], dacc[0][nt][2], dacc[0][nt][3],
                             a[0][0], a[0][1], a[0][2], a[0][3], b0, bb1);
                    mma16816(dacc[1][nt][0], dacc[1][nt][1], dacc[1][nt][2], dacc[1][nt][3],
                             a[1][0], a[1][1], a[1][2], a[1][3], b0, bb1);
                }
            }
        }

        if (half == 0) {
            __syncwarp();
#pragma unroll
            for (int nt = 0; nt < 8; nt++) {
                const float2 bp = *reinterpret_cast<const float2*>(s_npb + nt * 8 + 2 * qp);
#pragma unroll
                for (int mt = 0; mt < 2; mt++) {
#pragma unroll
                    for (int sdx = 0; sdx < 2; sdx++) {
                        const int rloc = mt * 16 + sdx * 8 + r0;
                        const int c = nt * 8 + qp * 2;
                        float2 v;
                        v.x = dacc[mt][nt][2 * sdx + 0] + bp.x;
                        v.y = dacc[mt][nt][2 * sdx + 1] + bp.y;
                        *reinterpret_cast<float2*>(A0w + rloc * 272 + c * 4) = v;
                    }
                }
            }
            __syncwarp();
        }
    }

#pragma unroll
    for (int nt = 0; nt < 8; nt++) {
        const float2 bp = *reinterpret_cast<const float2*>(s_npb + 64 + nt * 8 + 2 * qp);
#pragma unroll
        for (int mt = 0; mt < 2; mt++) {
#pragma unroll
            for (int sdx = 0; sdx < 2; sdx++) {
                dacc[mt][nt][2 * sdx + 0] += bp.x;
                dacc[mt][nt][2 * sdx + 1] += bp.y;
            }
        }
    }

#pragma unroll
    for (int j = 0; j < 4; j++) sum[j] = 0.0f;
#pragma unroll
    for (int nt = 0; nt < 8; nt++) {
#pragma unroll
        for (int mt = 0; mt < 2; mt++) {
#pragma unroll
            for (int sdx = 0; sdx < 2; sdx++) {
                const int j = mt * 2 + sdx;
                const int rloc = mt * 16 + sdx * 8 + r0;
                const float2 h0 = *reinterpret_cast<const float2*>(
                    A0w + rloc * 272 + (nt * 8 + qp * 2) * 4);
                sum[j] += h0.x + h0.y + dacc[mt][nt][2 * sdx] + dacc[mt][nt][2 * sdx + 1];
            }
        }
    }
#pragma unroll
    for (int j = 0; j < 4; j++) {
        sum[j] += __shfl_xor_sync(0xffffffffu, sum[j], 1);
        sum[j] += __shfl_xor_sync(0xffffffffu, sum[j], 2);
        mu[j] = sum[j] * (1.0f / 128.0f);
        sq[j] = 0.0f;
    }
#pragma unroll
    for (int nt = 0; nt < 8; nt++) {
#pragma unroll
        for (int mt = 0; mt < 2; mt++) {
#pragma unroll
            for (int sdx = 0; sdx < 2; sdx++) {
                const int j = mt * 2 + sdx;
                const int rloc = mt * 16 + sdx * 8 + r0;
                const float2 h0 = *reinterpret_cast<const float2*>(
                    A0w + rloc * 272 + (nt * 8 + qp * 2) * 4);
                const float d0 = h0.x - mu[j], d1 = h0.y - mu[j];
                const float d2 = dacc[mt][nt][2 * sdx] - mu[j];
                const float d3 = dacc[mt][nt][2 * sdx + 1] - mu[j];
                sq[j] += d0 * d0 + d1 * d1 + d2 * d2 + d3 * d3;
            }
        }
    }
#pragma unroll
    for (int j = 0; j < 4; j++) {
        sq[j] += __shfl_xor_sync(0xffffffffu, sq[j], 1);
        sq[j] += __shfl_xor_sync(0xffffffffu, sq[j], 2);
        rs[j] = rsqrtf(sq[j] * (1.0f / 128.0f) + 1e-5f);
    }

#pragma unroll
    for (int nt = 0; nt < 8; nt++) {
        const int c0 = nt * 8 + qp * 2;
        const int c1 = 64 + c0;
        const float2 g0 = __ldg(reinterpret_cast<const float2*>(ln_g + c0));
        const float2 b0 = __ldg(reinterpret_cast<const float2*>(ln_b + c0));
        const float2 g1 = __ldg(reinterpret_cast<const float2*>(ln_g + c1));
        const float2 b1v = __ldg(reinterpret_cast<const float2*>(ln_b + c1));
#pragma unroll
        for (int mt = 0; mt < 2; mt++) {
#pragma unroll
            for (int sdx = 0; sdx < 2; sdx++) {
                const int j = mt * 2 + sdx;
                const int rloc = mt * 16 + sdx * 8 + r0;
                const size_t orow = (size_t)(chunk * 32 + rloc) * OUTD;
                const float2 h0 = *reinterpret_cast<const float2*>(
                    A0w + rloc * 272 + c0 * 4);
                float2 o0, o1;
                o0.x = silu_f((h0.x - mu[j]) * rs[j] * g0.x + b0.x);
                o0.y = silu_f((h0.y - mu[j]) * rs[j] * g0.y + b0.y);
                o1.x = silu_f((dacc[mt][nt][2 * sdx] - mu[j]) * rs[j] * g1.x + b1v.x);
                o1.y = silu_f((dacc[mt][nt][2 * sdx + 1] - mu[j]) * rs[j] * g1.y + b1v.y);
                *reinterpret_cast<float2*>(out + orow + c0) = o0;
                *reinterpret_cast<float2*>(out + orow + c1) = o1;
            }
        }
    }
}

// ---------------------------------------------------------------------------
extern "C" void kernel_launch(void* const* d_in, const int* in_sizes, int n_in,
                              void* d_out, int out_size) {
    const float* pos    = (const float*)d_in[0];
    const float* zinc   = (const float*)d_in[1];
    const int*   ei     = (const int*)  d_in[2];
    const float* rbf_c  = (const float*)d_in[3];
    const float* rbf_w  = (const float*)d_in[4];
    const float* sh_w   = (const float*)d_in[5];
    const float* sh_b   = (const float*)d_in[6];
    const float* pm_w1  = (const float*)d_in[7];
    const float* pm_b1  = (const float*)d_in[8];
    const float* pm_w2  = (const float*)d_in[9];
    const float* pm_b2  = (const float*)d_in[10];
    const float* zn_w   = (const float*)d_in[11];
    const float* zn_b   = (const float*)d_in[12];
    const float* np_w   = (const float*)d_in[13];
    const float* np_b   = (const float*)d_in[14];
    const float* ln_g   = (const float*)d_in[15];
    const float* ln_b   = (const float*)d_in[16];
    float* out = (float*)d_out;

    static int attr_set = 0;
    if (!attr_set) {
        cudaFuncSetAttribute(edge_kernel,
                             cudaFuncAttributeMaxDynamicSharedMemorySize, SMEM_BYTES);
        cudaFuncSetAttribute(node_kernel,
                             cudaFuncAttributeMaxDynamicSharedMemorySize, NOD_SMEM);
        attr_set = 1;
    }

    zero_agg_kernel<<<(NNODES * HID / 4 + 255) / 256, 256>>>();

    edge_kernel<<<EDGE_BLOCKS, 32 * EDGE_NW, SMEM_BYTES>>>(
        pos, ei, rbf_c, rbf_w, sh_w, sh_b, pm_w1, pm_b1, pm_w2, pm_b2);

    node_kernel<<<NODE_BLOCKS, 128, NOD_SMEM>>>(
        pos, zinc, rbf_c, rbf_w, sh_w, sh_b, zn_w, zn_b, np_w, np_b,
        ln_g, ln_b, out);
}